// round 4
// baseline (speedup 1.0000x reference)
#include <cuda_runtime.h>
#include <cuda_bf16.h>
#include <math.h>

// Problem constants (fixed by setup_inputs)
#define BB   8
#define CC   2
#define TT   8
#define HH   512
#define WW   512
#define HW   (HH * WW)
#define NIMG (BB * TT)                       // 64
#define NPIX ((long long)NIMG * HW)          // 16,777,216
#define NQ   (NPIX / 4)                      // float4 groups
// mean denominator: N * C * H * W of the batched tensor = 64*2*512*512
#define DENOM ((double)NIMG * CC * HW)

__device__ double g_sum;

__global__ void init_kernel() { g_sum = 0.0; }

// Bilinear tap of a 2-channel image (planes p0, p1), zeros padding,
// align_corners=True pixel coords. Matches the jax reference exactly:
// floor/fractional weights, per-tap validity, clip-then-gather.
__device__ __forceinline__ void bilin2(const float* __restrict__ p0,
                                       const float* __restrict__ p1,
                                       float x, float y,
                                       float& o0, float& o1) {
    float x0f = floorf(x), y0f = floorf(y);
    float fx = x - x0f, fy = y - y0f;
    int x0 = (int)x0f, y0 = (int)y0f;
    int x1 = x0 + 1,   y1 = y0 + 1;

    bool vx0 = (x0 >= 0) & (x0 <= WW - 1);
    bool vx1 = (x1 >= 0) & (x1 <= WW - 1);
    bool vy0 = (y0 >= 0) & (y0 <= HH - 1);
    bool vy1 = (y1 >= 0) & (y1 <= HH - 1);

    int x0c = min(max(x0, 0), WW - 1);
    int x1c = min(max(x1, 0), WW - 1);
    int y0c = min(max(y0, 0), HH - 1);
    int y1c = min(max(y1, 0), HH - 1);

    float w00 = (1.0f - fx) * (1.0f - fy) * ((vx0 & vy0) ? 1.0f : 0.0f);
    float w10 = fx          * (1.0f - fy) * ((vx1 & vy0) ? 1.0f : 0.0f);
    float w01 = (1.0f - fx) * fy          * ((vx0 & vy1) ? 1.0f : 0.0f);
    float w11 = fx          * fy          * ((vx1 & vy1) ? 1.0f : 0.0f);

    int i00 = y0c * WW + x0c;
    int i10 = y0c * WW + x1c;
    int i01 = y1c * WW + x0c;
    int i11 = y1c * WW + x1c;

    o0 = w00 * __ldg(p0 + i00) + w10 * __ldg(p0 + i10) +
         w01 * __ldg(p0 + i01) + w11 * __ldg(p0 + i11);
    o1 = w00 * __ldg(p1 + i00) + w10 * __ldg(p1 + i10) +
         w01 * __ldg(p1 + i01) + w11 * __ldg(p1 + i11);
}

__global__ __launch_bounds__(256)
void loss_kernel(const float* __restrict__ flow,
                 const float* __restrict__ flowback,
                 const float* __restrict__ mask_fw,
                 const float* __restrict__ mask_bw) {
    const long long stride = (long long)gridDim.x * blockDim.x;
    float acc = 0.0f;

    for (long long q = (long long)blockIdx.x * blockDim.x + threadIdx.x;
         q < NQ; q += stride) {
        int img  = (int)(q / (HW / 4));
        int pix4 = (int)(q % (HW / 4)) * 4;
        int b = img / TT;
        int t = img % TT;

        // flow/flowback layout [B, C, T, H, W]; mask layout [B, 1, T, H, W]
        size_t base0 = ((size_t)(b * CC + 0) * TT + t) * HW;
        size_t base1 = ((size_t)(b * CC + 1) * TT + t) * HW;
        size_t basem = ((size_t)b * TT + t) * HW;

        const float* f0p  = flow     + base0;
        const float* f1p  = flow     + base1;
        const float* fb0p = flowback + base0;
        const float* fb1p = flowback + base1;

        float4 f0v  = *(const float4*)(f0p  + pix4);
        float4 f1v  = *(const float4*)(f1p  + pix4);
        float4 fb0v = *(const float4*)(fb0p + pix4);
        float4 fb1v = *(const float4*)(fb1p + pix4);
        float4 mfv  = *(const float4*)(mask_fw + basem + pix4);
        float4 mbv  = *(const float4*)(mask_bw + basem + pix4);

        int h = pix4 / WW;
        int w = pix4 % WW;
        float hf = (float)h;

        const float* f0a  = (const float*)&f0v;
        const float* f1a  = (const float*)&f1v;
        const float* fb0a = (const float*)&fb0v;
        const float* fb1a = (const float*)&fb1v;
        const float* mfa  = (const float*)&mfv;
        const float* mba  = (const float*)&mbv;

        #pragma unroll
        for (int j = 0; j < 4; j++) {
            float wf = (float)(w + j);
            float ff0 = f0a[j],  ff1 = f1a[j];
            float gb0 = fb0a[j], gb1 = fb1a[j];

            // nextloss: warp flowback by flow
            float wa0, wa1;
            bilin2(fb0p, fb1p, wf + ff0, hf + ff1, wa0, wa1);
            float termN = mfa[j] * (fabsf(wa0 + ff0) + fabsf(wa1 + ff1));

            // prevloss: warp flow by flowback
            float wb0, wb1;
            bilin2(f0p, f1p, wf + gb0, hf + gb1, wb0, wb1);
            float termP = mba[j] * (fabsf(wb0 + gb0) + fabsf(wb1 + gb1));

            acc += termN + termP;
        }
    }

    // warp reduce
    #pragma unroll
    for (int off = 16; off > 0; off >>= 1)
        acc += __shfl_xor_sync(0xFFFFFFFFu, acc, off);

    __shared__ float warp_sums[8];
    int lane = threadIdx.x & 31;
    int wid  = threadIdx.x >> 5;
    if (lane == 0) warp_sums[wid] = acc;
    __syncthreads();

    if (wid == 0) {
        float v = (lane < (blockDim.x >> 5)) ? warp_sums[lane] : 0.0f;
        #pragma unroll
        for (int off = 4; off > 0; off >>= 1)
            v += __shfl_xor_sync(0xFFFFFFFFu, v, off);
        if (lane == 0) atomicAdd(&g_sum, (double)v);
    }
}

__global__ void finalize_kernel(const int* __restrict__ npf_ptr,
                                float* __restrict__ out) {
    float scale = 8.0f;
    if (npf_ptr) {
        int iv = *npf_ptr;
        if (iv >= 1 && iv <= (1 << 20)) {
            scale = (float)iv;           // stored as int32 (or low word of int64)
        } else {
            float fv = __int_as_float(iv); // stored as float32
            scale = (fv > 0.0f && fv < 1.0e6f) ? fv : 8.0f;
        }
    }
    out[0] = (float)(g_sum / DENOM * (double)scale);
}

extern "C" void kernel_launch(void* const* d_in, const int* in_sizes, int n_in,
                              void* d_out, int out_size) {
    const float* flow     = (const float*)d_in[0];
    const float* flowback = (const float*)d_in[1];
    const float* mask_fw  = (const float*)d_in[2];
    const float* mask_bw  = (const float*)d_in[3];
    const int*   npf      = (n_in >= 5) ? (const int*)d_in[4] : nullptr;
    float* out = (float*)d_out;

    init_kernel<<<1, 1>>>();
    // 148 SMs * 8 blocks/SM, grid-stride over 4.2M float4 groups
    loss_kernel<<<148 * 8, 256>>>(flow, flowback, mask_fw, mask_bw);
    finalize_kernel<<<1, 1>>>(npf, out);
}

// round 5
// speedup vs baseline: 1.0014x; 1.0014x over previous
#include <cuda_runtime.h>
#include <cuda_bf16.h>
#include <math.h>

// Problem constants (fixed by setup_inputs)
#define BB   8
#define CC   2
#define TT   8
#define HH   512
#define WW   512
#define HW   (HH * WW)
#define NIMG (BB * TT)                       // 64
#define NPIX ((long long)NIMG * HW)          // 16,777,216
#define NQ   (NPIX / 4)                      // float4 groups
// mean denominator: N * C * H * W of the batched tensor = 64*2*512*512
#define DENOM ((double)NIMG * CC * HW)

__device__ double g_sum;

__global__ void init_kernel() { g_sum = 0.0; }

// Bilinear tap of a 2-channel image (planes p0, p1), zeros padding,
// align_corners=True pixel coords. Matches the jax reference exactly:
// floor/fractional weights, per-tap validity, clip-then-gather.
__device__ __forceinline__ void bilin2(const float* __restrict__ p0,
                                       const float* __restrict__ p1,
                                       float x, float y,
                                       float& o0, float& o1) {
    float x0f = floorf(x), y0f = floorf(y);
    float fx = x - x0f, fy = y - y0f;
    int x0 = (int)x0f, y0 = (int)y0f;
    int x1 = x0 + 1,   y1 = y0 + 1;

    bool vx0 = (x0 >= 0) & (x0 <= WW - 1);
    bool vx1 = (x1 >= 0) & (x1 <= WW - 1);
    bool vy0 = (y0 >= 0) & (y0 <= HH - 1);
    bool vy1 = (y1 >= 0) & (y1 <= HH - 1);

    int x0c = min(max(x0, 0), WW - 1);
    int x1c = min(max(x1, 0), WW - 1);
    int y0c = min(max(y0, 0), HH - 1);
    int y1c = min(max(y1, 0), HH - 1);

    float w00 = (1.0f - fx) * (1.0f - fy) * ((vx0 & vy0) ? 1.0f : 0.0f);
    float w10 = fx          * (1.0f - fy) * ((vx1 & vy0) ? 1.0f : 0.0f);
    float w01 = (1.0f - fx) * fy          * ((vx0 & vy1) ? 1.0f : 0.0f);
    float w11 = fx          * fy          * ((vx1 & vy1) ? 1.0f : 0.0f);

    int i00 = y0c * WW + x0c;
    int i10 = y0c * WW + x1c;
    int i01 = y1c * WW + x0c;
    int i11 = y1c * WW + x1c;

    o0 = w00 * __ldg(p0 + i00) + w10 * __ldg(p0 + i10) +
         w01 * __ldg(p0 + i01) + w11 * __ldg(p0 + i11);
    o1 = w00 * __ldg(p1 + i00) + w10 * __ldg(p1 + i10) +
         w01 * __ldg(p1 + i01) + w11 * __ldg(p1 + i11);
}

__global__ __launch_bounds__(256)
void loss_kernel(const float* __restrict__ flow,
                 const float* __restrict__ flowback,
                 const float* __restrict__ mask_fw,
                 const float* __restrict__ mask_bw) {
    const long long stride = (long long)gridDim.x * blockDim.x;
    float acc = 0.0f;

    for (long long q = (long long)blockIdx.x * blockDim.x + threadIdx.x;
         q < NQ; q += stride) {
        int img  = (int)(q / (HW / 4));
        int pix4 = (int)(q % (HW / 4)) * 4;
        int b = img / TT;
        int t = img % TT;

        // flow/flowback layout [B, C, T, H, W]; mask layout [B, 1, T, H, W]
        size_t base0 = ((size_t)(b * CC + 0) * TT + t) * HW;
        size_t base1 = ((size_t)(b * CC + 1) * TT + t) * HW;
        size_t basem = ((size_t)b * TT + t) * HW;

        const float* f0p  = flow     + base0;
        const float* f1p  = flow     + base1;
        const float* fb0p = flowback + base0;
        const float* fb1p = flowback + base1;

        float4 f0v  = *(const float4*)(f0p  + pix4);
        float4 f1v  = *(const float4*)(f1p  + pix4);
        float4 fb0v = *(const float4*)(fb0p + pix4);
        float4 fb1v = *(const float4*)(fb1p + pix4);
        float4 mfv  = *(const float4*)(mask_fw + basem + pix4);
        float4 mbv  = *(const float4*)(mask_bw + basem + pix4);

        int h = pix4 / WW;
        int w = pix4 % WW;
        float hf = (float)h;

        const float* f0a  = (const float*)&f0v;
        const float* f1a  = (const float*)&f1v;
        const float* fb0a = (const float*)&fb0v;
        const float* fb1a = (const float*)&fb1v;
        const float* mfa  = (const float*)&mfv;
        const float* mba  = (const float*)&mbv;

        #pragma unroll
        for (int j = 0; j < 4; j++) {
            float wf = (float)(w + j);
            float ff0 = f0a[j],  ff1 = f1a[j];
            float gb0 = fb0a[j], gb1 = fb1a[j];

            // nextloss: warp flowback by flow
            float wa0, wa1;
            bilin2(fb0p, fb1p, wf + ff0, hf + ff1, wa0, wa1);
            float termN = mfa[j] * (fabsf(wa0 + ff0) + fabsf(wa1 + ff1));

            // prevloss: warp flow by flowback
            float wb0, wb1;
            bilin2(f0p, f1p, wf + gb0, hf + gb1, wb0, wb1);
            float termP = mba[j] * (fabsf(wb0 + gb0) + fabsf(wb1 + gb1));

            acc += termN + termP;
        }
    }

    // warp reduce
    #pragma unroll
    for (int off = 16; off > 0; off >>= 1)
        acc += __shfl_xor_sync(0xFFFFFFFFu, acc, off);

    __shared__ float warp_sums[8];
    int lane = threadIdx.x & 31;
    int wid  = threadIdx.x >> 5;
    if (lane == 0) warp_sums[wid] = acc;
    __syncthreads();

    if (wid == 0) {
        float v = (lane < (blockDim.x >> 5)) ? warp_sums[lane] : 0.0f;
        #pragma unroll
        for (int off = 4; off > 0; off >>= 1)
            v += __shfl_xor_sync(0xFFFFFFFFu, v, off);
        if (lane == 0) atomicAdd(&g_sum, (double)v);
    }
}

__global__ void finalize_kernel(const int* __restrict__ npf_ptr,
                                float* __restrict__ out) {
    float scale = 8.0f;
    if (npf_ptr) {
        int iv = *npf_ptr;
        if (iv >= 1 && iv <= (1 << 20)) {
            scale = (float)iv;           // stored as int32 (or low word of int64)
        } else {
            float fv = __int_as_float(iv); // stored as float32
            scale = (fv > 0.0f && fv < 1.0e6f) ? fv : 8.0f;
        }
    }
    out[0] = (float)(g_sum / DENOM * (double)scale);
}

extern "C" void kernel_launch(void* const* d_in, const int* in_sizes, int n_in,
                              void* d_out, int out_size) {
    const float* flow     = (const float*)d_in[0];
    const float* flowback = (const float*)d_in[1];
    const float* mask_fw  = (const float*)d_in[2];
    const float* mask_bw  = (const float*)d_in[3];
    const int*   npf      = (n_in >= 5) ? (const int*)d_in[4] : nullptr;
    float* out = (float*)d_out;

    init_kernel<<<1, 1>>>();
    // 148 SMs * 8 blocks/SM, grid-stride over 4.2M float4 groups
    loss_kernel<<<148 * 8, 256>>>(flow, flowback, mask_fw, mask_bw);
    finalize_kernel<<<1, 1>>>(npf, out);
}

// round 6
// speedup vs baseline: 1.1510x; 1.1495x over previous
#include <cuda_runtime.h>
#include <cuda_bf16.h>
#include <math.h>

// Problem constants (fixed by setup_inputs)
#define BB   8
#define CC   2
#define TT   8
#define HH   512
#define WW   512
#define HW   (HH * WW)
#define NIMG (BB * TT)                       // 64
#define DENOM ((double)NIMG * CC * HW)

// Rolling-window parameters
#define STEP    4                            // pixel rows processed per iteration
#define WROWS   56                           // window rows: covers [h0-26, h0+STEP-1+26]
#define RSTRIDE 516                          // padded row stride (floats): 516 % 32 = 4
#define HALO_LO 26
#define HALO_HI 26                           // tap y1 = floor(y)+1 <= h+26 when dy <= 25

#define SMEM_BYTES (2 * WROWS * RSTRIDE * 4) // 231168 bytes

__device__ double g_sum;

__global__ void init_kernel() { g_sum = 0.0; }

// Global-memory bilinear fallback for taps outside the SMEM window (rare, ~0.2%).
__device__ __forceinline__ void taps_global(const float* __restrict__ p0,
                                            const float* __restrict__ p1,
                                            int i00, int i10, int i01, int i11,
                                            float& t00, float& t10, float& t01, float& t11,
                                            float& u00, float& u10, float& u01, float& u11) {
    t00 = __ldg(p0 + i00); t10 = __ldg(p0 + i10);
    t01 = __ldg(p0 + i01); t11 = __ldg(p0 + i11);
    u00 = __ldg(p1 + i00); u10 = __ldg(p1 + i10);
    u01 = __ldg(p1 + i01); u11 = __ldg(p1 + i11);
}

extern __shared__ float s_win[];             // [2 planes][WROWS][RSTRIDE]

__global__ __launch_bounds__(512)
void loss_kernel(const float* __restrict__ flow,
                 const float* __restrict__ flowback,
                 const float* __restrict__ mask_fw,
                 const float* __restrict__ mask_bw) {
    const int bx  = blockIdx.x;
    const int dir = bx & 1;                  // 0: nextloss (coords=flow, src=flowback)
    const int img = bx >> 1;                 // 1: prevloss (coords=flowback, src=flow)
    const int b = img / TT;
    const int t = img % TT;

    const size_t base0 = ((size_t)(b * CC + 0) * TT + t) * HW;
    const size_t base1 = ((size_t)(b * CC + 1) * TT + t) * HW;
    const size_t basem = ((size_t)b * TT + t) * HW;

    const float *c0p, *c1p, *s0p, *s1p, *mp;
    if (dir == 0) {
        c0p = flow + base0;     c1p = flow + base1;
        s0p = flowback + base0; s1p = flowback + base1;
        mp  = mask_fw + basem;
    } else {
        c0p = flowback + base0; c1p = flowback + base1;
        s0p = flow + base0;     s1p = flow + base1;
        mp  = mask_bw + basem;
    }

    float* sw0 = s_win;
    float* sw1 = s_win + WROWS * RSTRIDE;

    const int tid = threadIdx.x;             // 512 threads == WW columns
    float acc = 0.0f;
    int loaded_hi = -1;

    for (int h0 = 0; h0 < HH; h0 += STEP) {
        const int need_hi = min(HH - 1, h0 + STEP - 1 + HALO_HI);
        const int wlo = max(0, h0 - HALO_LO);

        __syncthreads();                     // previous chunk consumers done
        for (int r = loaded_hi + 1; r <= need_hi; r++) {
            const int slot = r % WROWS;
            sw0[slot * RSTRIDE + tid] = __ldg(s0p + (size_t)r * WW + tid);
            sw1[slot * RSTRIDE + tid] = __ldg(s1p + (size_t)r * WW + tid);
        }
        loaded_hi = need_hi;
        __syncthreads();                     // window ready

        const int whi = loaded_hi;

        #pragma unroll
        for (int r = 0; r < STEP; r++) {
            const int h = h0 + r;
            const size_t idx = (size_t)h * WW + tid;
            const float c0 = __ldg(c0p + idx);
            const float c1 = __ldg(c1p + idx);
            const float m  = __ldg(mp  + idx);

            const float x = (float)tid + c0;
            const float y = (float)h   + c1;
            const float x0f = floorf(x), y0f = floorf(y);
            const float fx = x - x0f, fy = y - y0f;
            const int x0 = (int)x0f, y0 = (int)y0f;
            const int x1 = x0 + 1,   y1 = y0 + 1;

            const bool vx0 = (x0 >= 0) & (x0 <= WW - 1);
            const bool vx1 = (x1 >= 0) & (x1 <= WW - 1);
            const bool vy0 = (y0 >= 0) & (y0 <= HH - 1);
            const bool vy1 = (y1 >= 0) & (y1 <= HH - 1);

            const int x0c = min(max(x0, 0), WW - 1);
            const int x1c = min(max(x1, 0), WW - 1);
            const int y0c = min(max(y0, 0), HH - 1);
            const int y1c = min(max(y1, 0), HH - 1);

            const float w00 = (1.0f - fx) * (1.0f - fy) * ((vx0 & vy0) ? 1.0f : 0.0f);
            const float w10 = fx          * (1.0f - fy) * ((vx1 & vy0) ? 1.0f : 0.0f);
            const float w01 = (1.0f - fx) * fy          * ((vx0 & vy1) ? 1.0f : 0.0f);
            const float w11 = fx          * fy          * ((vx1 & vy1) ? 1.0f : 0.0f);

            float t00, t10, t01, t11, u00, u10, u01, u11;
            if (y0c >= wlo && y1c <= whi) {
                const int s0 = (y0c % WROWS) * RSTRIDE;
                const int s1 = (y1c % WROWS) * RSTRIDE;
                t00 = sw0[s0 + x0c]; t10 = sw0[s0 + x1c];
                t01 = sw0[s1 + x0c]; t11 = sw0[s1 + x1c];
                u00 = sw1[s0 + x0c]; u10 = sw1[s0 + x1c];
                u01 = sw1[s1 + x0c]; u11 = sw1[s1 + x1c];
            } else {
                const int i00 = y0c * WW + x0c, i10 = y0c * WW + x1c;
                const int i01 = y1c * WW + x0c, i11 = y1c * WW + x1c;
                taps_global(s0p, s1p, i00, i10, i01, i11,
                            t00, t10, t01, t11, u00, u10, u01, u11);
            }

            const float wv0 = w00 * t00 + w10 * t10 + w01 * t01 + w11 * t11;
            const float wv1 = w00 * u00 + w10 * u10 + w01 * u01 + w11 * u11;
            acc += m * (fabsf(wv0 + c0) + fabsf(wv1 + c1));
        }
    }

    // Block reduction: warp shuffle, then cross-warp, one double atomic per block.
    #pragma unroll
    for (int off = 16; off > 0; off >>= 1)
        acc += __shfl_xor_sync(0xFFFFFFFFu, acc, off);

    __shared__ float warp_sums[16];
    const int lane = tid & 31;
    const int wid  = tid >> 5;
    if (lane == 0) warp_sums[wid] = acc;
    __syncthreads();

    if (wid == 0) {
        float v = (lane < 16) ? warp_sums[lane] : 0.0f;
        #pragma unroll
        for (int off = 8; off > 0; off >>= 1)
            v += __shfl_xor_sync(0xFFFFFFFFu, v, off);
        if (lane == 0) atomicAdd(&g_sum, (double)v);
    }
}

__global__ void finalize_kernel(const int* __restrict__ npf_ptr,
                                float* __restrict__ out) {
    float scale = 8.0f;
    if (npf_ptr) {
        int iv = *npf_ptr;
        if (iv >= 1 && iv <= (1 << 20)) {
            scale = (float)iv;               // stored as int32 (or low word of int64)
        } else {
            float fv = __int_as_float(iv);   // stored as float32
            scale = (fv > 0.0f && fv < 1.0e6f) ? fv : 8.0f;
        }
    }
    out[0] = (float)(g_sum / DENOM * (double)scale);
}

extern "C" void kernel_launch(void* const* d_in, const int* in_sizes, int n_in,
                              void* d_out, int out_size) {
    const float* flow     = (const float*)d_in[0];
    const float* flowback = (const float*)d_in[1];
    const float* mask_fw  = (const float*)d_in[2];
    const float* mask_bw  = (const float*)d_in[3];
    const int*   npf      = (n_in >= 5) ? (const int*)d_in[4] : nullptr;
    float* out = (float*)d_out;

    static bool attr_set = false;  // idempotent attribute set (same every call)
    cudaFuncSetAttribute(loss_kernel,
                         cudaFuncAttributeMaxDynamicSharedMemorySize, SMEM_BYTES);
    (void)attr_set;

    init_kernel<<<1, 1>>>();
    // 64 images x 2 directions, one block each; one wave on 148 SMs.
    loss_kernel<<<NIMG * 2, 512, SMEM_BYTES>>>(flow, flowback, mask_fw, mask_bw);
    finalize_kernel<<<1, 1>>>(npf, out);
}

// round 7
// speedup vs baseline: 1.9077x; 1.6574x over previous
#include <cuda_runtime.h>
#include <cuda_bf16.h>
#include <math.h>

// Problem constants (fixed by setup_inputs)
#define BB   8
#define CC   2
#define TT   8
#define HH   512
#define WW   512
#define HW   (HH * WW)
#define NIMG (BB * TT)                       // 64
#define DENOM ((double)NIMG * CC * HW)

// Rolling-window parameters
#define STEP    4                            // pixel rows per chunk
#define WROWS   56                           // window rows: [h0-26, h0+29]
#define RSTRIDE 516                          // float2 per row; 516*2 % 32 != 0 (conflict-free row offset)
#define HALO    26

#define NBLK    148                          // one block per SM, persistent
#define GTOT    (NIMG * 2 * HH)              // 65536 flattened (img,dir,row) units

#define SMEM_BYTES (WROWS * RSTRIDE * 8)     // 231168 bytes (float2 window)

__device__ double g_sum;

__global__ void init_kernel() { g_sum = 0.0; }

extern __shared__ float2 s_win[];            // [WROWS][RSTRIDE], .x=plane0 .y=plane1

__device__ __forceinline__ void sts_val(int r, int col, int rp, float v) {
    ((float*)s_win)[((r % WROWS) * RSTRIDE + col) * 2 + rp] = v;
}

__global__ __launch_bounds__(1024, 1)
void loss_kernel(const float* __restrict__ flow,
                 const float* __restrict__ flowback,
                 const float* __restrict__ mask_fw,
                 const float* __restrict__ mask_bw) {
    const int tid = threadIdx.x;
    const int col = tid & (WW - 1);          // 0..511
    const int rp  = tid >> 9;                // 0/1: staging plane + row parity

    int g    = (int)(((long long)blockIdx.x       * GTOT) / NBLK);
    int g_hi = (int)(((long long)(blockIdx.x + 1) * GTOT) / NBLK);

    float acc = 0.0f;

    while (g < g_hi) {
        const int ctx = g >> 9;              // 512 rows per (img,dir) context
        const int rlo = g & (HH - 1);
        const int seg = min(HH - rlo, g_hi - g);
        const int rhi = rlo + seg;
        g += seg;

        const int img = ctx >> 1;
        const int dir = ctx & 1;             // 0: coords=flow,src=flowback; 1: swapped
        const int b = img / TT, t = img % TT;

        const size_t base0 = ((size_t)(b * CC + 0) * TT + t) * HW;
        const size_t base1 = ((size_t)(b * CC + 1) * TT + t) * HW;
        const size_t basem = ((size_t)b * TT + t) * HW;

        const float *c0p, *c1p, *s0p, *s1p, *mp;
        if (dir == 0) {
            c0p = flow + base0;     c1p = flow + base1;
            s0p = flowback + base0; s1p = flowback + base1;
            mp  = mask_fw + basem;
        } else {
            c0p = flowback + base0; c1p = flowback + base1;
            s0p = flow + base0;     s1p = flow + base1;
            mp  = mask_bw + basem;
        }
        const float* sp = rp ? s1p : s0p;    // this thread's staging plane

        // ---- prologue: direct-load rows [rlo-26, rlo+25] into window (MLP=8 batches) ----
        {
            const int plo = max(0, rlo - HALO);
            const int phi = min(HH - 1, rlo + 25);
            __syncthreads();                 // prior segment done with window
            for (int r0 = plo; r0 <= phi; r0 += 8) {
                float v[8];
                #pragma unroll
                for (int k = 0; k < 8; k++) {
                    int r = min(r0 + k, phi);
                    v[k] = sp[(size_t)r * WW + col];
                }
                #pragma unroll
                for (int k = 0; k < 8; k++) {
                    int r = r0 + k;
                    if (r <= phi) sts_val(r, col, rp, v[k]);
                }
            }
        }

        // ---- prefetch first chunk: source rows [rlo+26, rlo+29] + coords rows [rlo, rlo+3] ----
        float sv[4];
        #pragma unroll
        for (int k = 0; k < 4; k++) {
            int r = min(rlo + HALO + k, HH - 1);
            sv[k] = sp[(size_t)r * WW + col];
        }
        float pc0[2], pc1[2], pm[2];
        #pragma unroll
        for (int s = 0; s < 2; s++) {
            int r = min(rlo + 2 * s + rp, HH - 1);
            size_t o = (size_t)r * WW + col;
            pc0[s] = c0p[o]; pc1[s] = c1p[o]; pm[s] = mp[o];
        }

        for (int h0 = rlo; h0 < rhi; h0 += STEP) {
            __syncthreads();                 // consumers done with slots being replaced
            // commit staged source rows [h0+26, h0+29]
            #pragma unroll
            for (int k = 0; k < 4; k++) {
                int r = h0 + HALO + k;
                if (r < HH) sts_val(r, col, rp, sv[k]);
            }
            // current coords
            float cc0[2], cc1[2], cm[2];
            #pragma unroll
            for (int s = 0; s < 2; s++) { cc0[s] = pc0[s]; cc1[s] = pc1[s]; cm[s] = pm[s]; }
            // issue prefetch for next chunk (completes during compute below)
            #pragma unroll
            for (int k = 0; k < 4; k++) {
                int r = min(h0 + HALO + STEP + k, HH - 1);
                sv[k] = sp[(size_t)r * WW + col];
            }
            #pragma unroll
            for (int s = 0; s < 2; s++) {
                int r = min(h0 + STEP + 2 * s + rp, HH - 1);
                size_t o = (size_t)r * WW + col;
                pc0[s] = c0p[o]; pc1[s] = c1p[o]; pm[s] = mp[o];
            }
            __syncthreads();                 // window ready

            const int wlo = max(0, h0 - HALO);
            const int whi = min(HH - 1, h0 + STEP - 1 + HALO);

            #pragma unroll
            for (int s = 0; s < 2; s++) {
                const int h = h0 + 2 * s + rp;
                if (h >= rhi) continue;
                const float c0 = cc0[s], c1 = cc1[s], m = cm[s];

                const float x = (float)col + c0;
                const float y = (float)h   + c1;
                const float x0f = floorf(x), y0f = floorf(y);
                const float fx = x - x0f, fy = y - y0f;
                const int x0 = (int)x0f, y0 = (int)y0f;
                const int x1 = x0 + 1,   y1 = y0 + 1;

                const bool vx0 = (x0 >= 0) & (x0 <= WW - 1);
                const bool vx1 = (x1 >= 0) & (x1 <= WW - 1);
                const bool vy0 = (y0 >= 0) & (y0 <= HH - 1);
                const bool vy1 = (y1 >= 0) & (y1 <= HH - 1);

                const int x0c = min(max(x0, 0), WW - 1);
                const int x1c = min(max(x1, 0), WW - 1);
                const int y0c = min(max(y0, 0), HH - 1);
                const int y1c = min(max(y1, 0), HH - 1);

                const float w00 = (1.0f - fx) * (1.0f - fy) * ((vx0 & vy0) ? 1.0f : 0.0f);
                const float w10 = fx          * (1.0f - fy) * ((vx1 & vy0) ? 1.0f : 0.0f);
                const float w01 = (1.0f - fx) * fy          * ((vx0 & vy1) ? 1.0f : 0.0f);
                const float w11 = fx          * fy          * ((vx1 & vy1) ? 1.0f : 0.0f);

                float2 v00, v10, v01, v11;
                if (y0c >= wlo && y1c <= whi) {
                    const int s0 = (y0c % WROWS) * RSTRIDE;
                    const int s1 = (y1c % WROWS) * RSTRIDE;
                    v00 = s_win[s0 + x0c]; v10 = s_win[s0 + x1c];
                    v01 = s_win[s1 + x0c]; v11 = s_win[s1 + x1c];
                } else {                     // rare (~0.2%) out-of-window fallback
                    const int i00 = y0c * WW + x0c, i10 = y0c * WW + x1c;
                    const int i01 = y1c * WW + x0c, i11 = y1c * WW + x1c;
                    v00 = make_float2(__ldg(s0p + i00), __ldg(s1p + i00));
                    v10 = make_float2(__ldg(s0p + i10), __ldg(s1p + i10));
                    v01 = make_float2(__ldg(s0p + i01), __ldg(s1p + i01));
                    v11 = make_float2(__ldg(s0p + i11), __ldg(s1p + i11));
                }

                const float wv0 = w00 * v00.x + w10 * v10.x + w01 * v01.x + w11 * v11.x;
                const float wv1 = w00 * v00.y + w10 * v10.y + w01 * v01.y + w11 * v11.y;
                acc += m * (fabsf(wv0 + c0) + fabsf(wv1 + c1));
            }
        }
    }

    // Block reduction: warp shuffle, cross-warp via static smem, one double atomic/block.
    #pragma unroll
    for (int off = 16; off > 0; off >>= 1)
        acc += __shfl_xor_sync(0xFFFFFFFFu, acc, off);

    __shared__ float warp_sums[32];
    const int lane = tid & 31;
    const int wid  = tid >> 5;
    if (lane == 0) warp_sums[wid] = acc;
    __syncthreads();

    if (wid == 0) {
        float v = warp_sums[lane];
        #pragma unroll
        for (int off = 16; off > 0; off >>= 1)
            v += __shfl_xor_sync(0xFFFFFFFFu, v, off);
        if (lane == 0) atomicAdd(&g_sum, (double)v);
    }
}

__global__ void finalize_kernel(const int* __restrict__ npf_ptr,
                                float* __restrict__ out) {
    float scale = 8.0f;
    if (npf_ptr) {
        int iv = *npf_ptr;
        if (iv >= 1 && iv <= (1 << 20)) {
            scale = (float)iv;               // stored as int32 (or low word of int64)
        } else {
            float fv = __int_as_float(iv);   // stored as float32
            scale = (fv > 0.0f && fv < 1.0e6f) ? fv : 8.0f;
        }
    }
    out[0] = (float)(g_sum / DENOM * (double)scale);
}

extern "C" void kernel_launch(void* const* d_in, const int* in_sizes, int n_in,
                              void* d_out, int out_size) {
    const float* flow     = (const float*)d_in[0];
    const float* flowback = (const float*)d_in[1];
    const float* mask_fw  = (const float*)d_in[2];
    const float* mask_bw  = (const float*)d_in[3];
    const int*   npf      = (n_in >= 5) ? (const int*)d_in[4] : nullptr;
    float* out = (float*)d_out;

    cudaFuncSetAttribute(loss_kernel,
                         cudaFuncAttributeMaxDynamicSharedMemorySize, SMEM_BYTES);

    init_kernel<<<1, 1>>>();
    loss_kernel<<<NBLK, 1024, SMEM_BYTES>>>(flow, flowback, mask_fw, mask_bw);
    finalize_kernel<<<1, 1>>>(npf, out);
}

// round 8
// speedup vs baseline: 2.2868x; 1.1988x over previous
#include <cuda_runtime.h>
#include <cuda_fp16.h>
#include <math.h>

// Problem constants (fixed by setup_inputs)
#define BB   8
#define CC   2
#define TT   8
#define HH   512
#define WW   512
#define HW   (HH * WW)
#define NIMG (BB * TT)                        // 64
#define DENOM ((double)NIMG * CC * HW)

// Rolling-window parameters
#define STEP    4                             // pixel rows per chunk
#define HALO    24                            // one-sided halo; fallback ~0.3%
#define WROWS   56                            // ring rows (= 2*HALO + 2*STEP)
#define RSTRIDE 516                           // half2 per row; 516 % 32 = 4 (row stagger)

#define NBLK    296                           // 2 persistent blocks per SM
#define GTOT    (NIMG * 2 * HH)               // 65536 flattened (img,dir,row) units

#define SMEM_BYTES (WROWS * RSTRIDE * 4)      // 115,584 B -> 2 blocks/SM

__device__ double g_sum;

__global__ void init_kernel() { g_sum = 0.0; }

extern __shared__ __half2 s_win[];            // [WROWS][RSTRIDE], (ch0, ch1) packed

__global__ __launch_bounds__(512, 2)
void loss_kernel(const float* __restrict__ flow,
                 const float* __restrict__ flowback,
                 const float* __restrict__ mask_fw,
                 const float* __restrict__ mask_bw) {
    const int tid = threadIdx.x;              // == column, 0..511

    int g    = (int)(((long long)blockIdx.x       * GTOT) / NBLK);
    int g_hi = (int)(((long long)(blockIdx.x + 1) * GTOT) / NBLK);

    float acc = 0.0f;

    while (g < g_hi) {
        const int ctx = g >> 9;               // 512 rows per (img,dir) context
        const int rlo = g & (HH - 1);
        const int seg = min(HH - rlo, g_hi - g);
        const int rhi = rlo + seg;
        g += seg;

        const int img = ctx >> 1;
        const int dir = ctx & 1;              // 0: coords=flow,src=flowback; 1: swapped
        const int b = img / TT, t = img % TT;

        const size_t base0 = ((size_t)(b * CC + 0) * TT + t) * HW;
        const size_t base1 = ((size_t)(b * CC + 1) * TT + t) * HW;
        const size_t basem = ((size_t)b * TT + t) * HW;

        const float *c0p, *c1p, *s0p, *s1p, *mp;
        if (dir == 0) {
            c0p = flow + base0;     c1p = flow + base1;
            s0p = flowback + base0; s1p = flowback + base1;
            mp  = mask_fw + basem;
        } else {
            c0p = flowback + base0; c1p = flowback + base1;
            s0p = flow + base0;     s1p = flow + base1;
            mp  = mask_bw + basem;
        }

        // ---- prologue: stage rows [rlo-HALO, rlo+HALO-1] (f32 -> half2), MLP=8 ----
        {
            const int plo = max(0, rlo - HALO);
            const int phi = min(HH - 1, rlo + HALO - 1);
            __syncthreads();                  // prior segment done with window
            for (int r0 = plo; r0 <= phi; r0 += 8) {
                float a0[8], a1[8];
                #pragma unroll
                for (int k = 0; k < 8; k++) {
                    int r = min(r0 + k, phi);
                    a0[k] = s0p[(size_t)r * WW + tid];
                    a1[k] = s1p[(size_t)r * WW + tid];
                }
                #pragma unroll
                for (int k = 0; k < 8; k++) {
                    int r = r0 + k;
                    if (r <= phi)
                        s_win[(r % WROWS) * RSTRIDE + tid] =
                            __floats2half2_rn(a0[k], a1[k]);
                }
            }
        }

        // ---- prefetch first chunk's staged source rows [rlo+HALO, rlo+HALO+3] ----
        float sv0[4], sv1[4];
        #pragma unroll
        for (int k = 0; k < 4; k++) {
            int r = min(rlo + HALO + k, HH - 1);
            sv0[k] = s0p[(size_t)r * WW + tid];
            sv1[k] = s1p[(size_t)r * WW + tid];
        }

        for (int h0 = rlo; h0 < rhi; h0 += STEP) {
            __syncthreads();                  // consumers done with slots being replaced
            // commit staged source rows [h0+HALO, h0+HALO+3]
            #pragma unroll
            for (int k = 0; k < 4; k++) {
                int r = h0 + HALO + k;
                if (r < HH)
                    s_win[(r % WROWS) * RSTRIDE + tid] =
                        __floats2half2_rn(sv0[k], sv1[k]);
            }
            // prefetch next chunk's staged rows (completes during compute)
            #pragma unroll
            for (int k = 0; k < 4; k++) {
                int r = min(h0 + HALO + STEP + k, HH - 1);
                sv0[k] = s0p[(size_t)r * WW + tid];
                sv1[k] = s1p[(size_t)r * WW + tid];
            }
            __syncthreads();                  // window ready

            const int wlo   = max(0, h0 - HALO);
            const int whi   = min(HH - 1, h0 + STEP - 1 + HALO);
            const unsigned bslot  = (unsigned)(wlo % WROWS);
            const unsigned hibnd  = (unsigned)(HH - 1 - whi);   // 0 when whi==511

            // batched coords/mask loads for this chunk (MLP=12)
            float cc0[4], cc1[4], cm[4];
            #pragma unroll
            for (int s = 0; s < 4; s++) {
                int r = min(h0 + s, HH - 1);
                size_t o = (size_t)r * WW + tid;
                cc0[s] = c0p[o]; cc1[s] = c1p[o]; cm[s] = mp[o];
            }

            #pragma unroll
            for (int s = 0; s < 4; s++) {
                const int h = h0 + s;
                if (h >= rhi) continue;
                const float c0 = cc0[s], c1 = cc1[s], m = cm[s];

                const float x = (float)tid + c0;
                const float y = (float)h   + c1;
                const float x0f = floorf(x), y0f = floorf(y);
                const float fx = x - x0f, fy = y - y0f;
                const int x0 = (int)x0f, y0 = (int)y0f;
                const int x1 = x0 + 1,   y1 = y0 + 1;

                // 1-D weight factors masked by image validity (unsigned range test)
                const float wx0 = ((unsigned)x0 < WW) ? (1.0f - fx) : 0.0f;
                const float wx1 = ((unsigned)x1 < WW) ? fx          : 0.0f;
                const float wy0 = ((unsigned)y0 < HH) ? (1.0f - fy) : 0.0f;
                const float wy1 = ((unsigned)y1 < HH) ? fy          : 0.0f;

                // fallback iff some tap row is in-image but outside the window
                const bool fb = ((unsigned)y0 < (unsigned)wlo) |
                                ((unsigned)y1 < (unsigned)wlo) |
                                ((unsigned)(y0 - whi - 1) < hibnd) |
                                ((unsigned)(y1 - whi - 1) < hibnd);

                float wv0, wv1;
                if (!fb) {
                    const int x0c = min(max(x0, 0), WW - 1);
                    const int x1c = min(max(x1, 0), WW - 1);
                    const int y0c = min(max(y0, wlo), whi);
                    const int y1c = min(max(y1, wlo), whi);
                    unsigned r0 = bslot + (unsigned)(y0c - wlo);
                    unsigned r1 = bslot + (unsigned)(y1c - wlo);
                    r0 = min(r0, r0 - WROWS);       // branch-free ring wrap
                    r1 = min(r1, r1 - WROWS);

                    const __half2 v00 = s_win[r0 * RSTRIDE + x0c];
                    const __half2 v10 = s_win[r0 * RSTRIDE + x1c];
                    const __half2 v01 = s_win[r1 * RSTRIDE + x0c];
                    const __half2 v11 = s_win[r1 * RSTRIDE + x1c];

                    const __half2 w00h = __float2half2_rn(wx0 * wy0);
                    const __half2 w10h = __float2half2_rn(wx1 * wy0);
                    const __half2 w01h = __float2half2_rn(wx0 * wy1);
                    const __half2 w11h = __float2half2_rn(wx1 * wy1);

                    __half2 a2 = __hmul2(w00h, v00);
                    a2 = __hfma2(w10h, v10, a2);
                    a2 = __hfma2(w01h, v01, a2);
                    a2 = __hfma2(w11h, v11, a2);
                    wv0 = __low2float(a2);
                    wv1 = __high2float(a2);
                } else {                           // rare (~0.3%) exact fp32 path
                    const int x0c = min(max(x0, 0), WW - 1);
                    const int x1c = min(max(x1, 0), WW - 1);
                    const int y0i = min(max(y0, 0), HH - 1);
                    const int y1i = min(max(y1, 0), HH - 1);
                    const int i00 = y0i * WW + x0c, i10 = y0i * WW + x1c;
                    const int i01 = y1i * WW + x0c, i11 = y1i * WW + x1c;
                    const float w00 = wx0 * wy0, w10 = wx1 * wy0;
                    const float w01 = wx0 * wy1, w11 = wx1 * wy1;
                    wv0 = w00 * __ldg(s0p + i00) + w10 * __ldg(s0p + i10) +
                          w01 * __ldg(s0p + i01) + w11 * __ldg(s0p + i11);
                    wv1 = w00 * __ldg(s1p + i00) + w10 * __ldg(s1p + i10) +
                          w01 * __ldg(s1p + i01) + w11 * __ldg(s1p + i11);
                }

                acc += m * (fabsf(wv0 + c0) + fabsf(wv1 + c1));
            }
        }
    }

    // Block reduction: warp shuffle, cross-warp, one double atomic per block.
    #pragma unroll
    for (int off = 16; off > 0; off >>= 1)
        acc += __shfl_xor_sync(0xFFFFFFFFu, acc, off);

    __shared__ float warp_sums[16];
    const int lane = tid & 31;
    const int wid  = tid >> 5;
    if (lane == 0) warp_sums[wid] = acc;
    __syncthreads();

    if (wid == 0) {
        float v = warp_sums[lane & 15];
        #pragma unroll
        for (int off = 8; off > 0; off >>= 1)
            v += __shfl_xor_sync(0xFFFFFFFFu, v, off);
        if (lane == 0) atomicAdd(&g_sum, (double)v);
    }
}

__global__ void finalize_kernel(const int* __restrict__ npf_ptr,
                                float* __restrict__ out) {
    float scale = 8.0f;
    if (npf_ptr) {
        int iv = *npf_ptr;
        if (iv >= 1 && iv <= (1 << 20)) {
            scale = (float)iv;                // stored as int32 (or low word of int64)
        } else {
            float fv = __int_as_float(iv);    // stored as float32
            scale = (fv > 0.0f && fv < 1.0e6f) ? fv : 8.0f;
        }
    }
    out[0] = (float)(g_sum / DENOM * (double)scale);
}

extern "C" void kernel_launch(void* const* d_in, const int* in_sizes, int n_in,
                              void* d_out, int out_size) {
    const float* flow     = (const float*)d_in[0];
    const float* flowback = (const float*)d_in[1];
    const float* mask_fw  = (const float*)d_in[2];
    const float* mask_bw  = (const float*)d_in[3];
    const int*   npf      = (n_in >= 5) ? (const int*)d_in[4] : nullptr;
    float* out = (float*)d_out;

    cudaFuncSetAttribute(loss_kernel,
                         cudaFuncAttributeMaxDynamicSharedMemorySize, SMEM_BYTES);

    init_kernel<<<1, 1>>>();
    loss_kernel<<<NBLK, 512, SMEM_BYTES>>>(flow, flowback, mask_fw, mask_bw);
    finalize_kernel<<<1, 1>>>(npf, out);
}

// round 9
// speedup vs baseline: 2.3499x; 1.0276x over previous
#include <cuda_runtime.h>
#include <cuda_fp16.h>
#include <math.h>

// Problem constants (fixed by setup_inputs)
#define BB   8
#define CC   2
#define TT   8
#define HH   512
#define WW   512
#define HW   (HH * WW)
#define NIMG (BB * TT)                        // 64
#define DENOM ((double)NIMG * CC * HW)

// Rolling-window parameters
#define STEP    4                             // pixel rows per chunk
#define HALO    24                            // one-sided halo; fallback ~0.4%
#define WROWS   56                            // ring rows (= 2*HALO + 2*STEP)
#define RSTRIDE 516                           // half2 per row; 516 % 32 = 4 (row stagger)

#define NPAIR   148                           // one block-pair per SM
#define NBLK    (2 * NPAIR)                   // dir0 wave + dir1 wave
#define PTOT    (NIMG * HH)                   // 32768 flattened (img,row) units

#define SMEM_BYTES (WROWS * RSTRIDE * 4)      // 115,584 B -> 2 blocks/SM

__device__ double g_sum;

__global__ void init_kernel() { g_sum = 0.0; }

extern __shared__ __half2 s_win[];            // [WROWS][RSTRIDE], (ch0, ch1) packed

__global__ __launch_bounds__(512, 2)
void loss_kernel(const float* __restrict__ flow,
                 const float* __restrict__ flowback,
                 const float* __restrict__ mask_fw,
                 const float* __restrict__ mask_bw) {
    const int tid = threadIdx.x;              // == column, 0..511

    // Direction-paired mapping: blocks p and p+148 are co-resident on the same
    // SM (wave-1/wave-2) and cover the SAME (img,row) range with opposite roles,
    // so dir0's coordinate stream is dir1's staged-source stream -> L2 reuse.
    const int dir  = (blockIdx.x >= NPAIR) ? 1 : 0;
    const int pair = blockIdx.x - dir * NPAIR;

    int g    = (int)(((long long)pair       * PTOT) / NPAIR);
    int g_hi = (int)(((long long)(pair + 1) * PTOT) / NPAIR);

    float acc = 0.0f;

    while (g < g_hi) {
        const int img = g >> 9;               // 512 rows per image
        const int rlo = g & (HH - 1);
        const int seg = min(HH - rlo, g_hi - g);
        const int rhi = rlo + seg;
        g += seg;

        const int b = img / TT, t = img % TT;

        const size_t base0 = ((size_t)(b * CC + 0) * TT + t) * HW;
        const size_t base1 = ((size_t)(b * CC + 1) * TT + t) * HW;
        const size_t basem = ((size_t)b * TT + t) * HW;

        const float *c0p, *c1p, *s0p, *s1p, *mp;
        if (dir == 0) {
            c0p = flow + base0;     c1p = flow + base1;
            s0p = flowback + base0; s1p = flowback + base1;
            mp  = mask_fw + basem;
        } else {
            c0p = flowback + base0; c1p = flowback + base1;
            s0p = flow + base0;     s1p = flow + base1;
            mp  = mask_bw + basem;
        }

        // ---- prologue: stage rows [rlo-HALO, rlo+HALO-1] (f32 -> half2), MLP=8 ----
        {
            const int plo = max(0, rlo - HALO);
            const int phi = min(HH - 1, rlo + HALO - 1);
            __syncthreads();                  // prior segment done with window
            for (int r0 = plo; r0 <= phi; r0 += 8) {
                float a0[8], a1[8];
                #pragma unroll
                for (int k = 0; k < 8; k++) {
                    int r = min(r0 + k, phi);
                    a0[k] = s0p[(size_t)r * WW + tid];
                    a1[k] = s1p[(size_t)r * WW + tid];
                }
                #pragma unroll
                for (int k = 0; k < 8; k++) {
                    int r = r0 + k;
                    if (r <= phi)
                        s_win[(r % WROWS) * RSTRIDE + tid] =
                            __floats2half2_rn(a0[k], a1[k]);
                }
            }
        }

        // ---- prefetch first chunk's staged source rows [rlo+HALO, rlo+HALO+3] ----
        float sv0[4], sv1[4];
        #pragma unroll
        for (int k = 0; k < 4; k++) {
            int r = min(rlo + HALO + k, HH - 1);
            sv0[k] = s0p[(size_t)r * WW + tid];
            sv1[k] = s1p[(size_t)r * WW + tid];
        }

        for (int h0 = rlo; h0 < rhi; h0 += STEP) {
            __syncthreads();                  // consumers done with slots being replaced
            // commit staged source rows [h0+HALO, h0+HALO+3]
            #pragma unroll
            for (int k = 0; k < 4; k++) {
                int r = h0 + HALO + k;
                if (r < HH)
                    s_win[(r % WROWS) * RSTRIDE + tid] =
                        __floats2half2_rn(sv0[k], sv1[k]);
            }
            // prefetch next chunk's staged rows (completes during compute)
            #pragma unroll
            for (int k = 0; k < 4; k++) {
                int r = min(h0 + HALO + STEP + k, HH - 1);
                sv0[k] = s0p[(size_t)r * WW + tid];
                sv1[k] = s1p[(size_t)r * WW + tid];
            }
            // coord/mask loads issued in the barrier shadow: their DRAM latency
            // overlaps the STS commits + sync2 drain instead of stalling compute.
            float cc0[4], cc1[4], cm[4];
            #pragma unroll
            for (int s = 0; s < 4; s++) {
                int r = min(h0 + s, HH - 1);
                size_t o = (size_t)r * WW + tid;
                cc0[s] = c0p[o]; cc1[s] = c1p[o]; cm[s] = mp[o];
            }
            __syncthreads();                  // window ready

            const int wlo   = max(0, h0 - HALO);
            const int whi   = min(HH - 1, h0 + STEP - 1 + HALO);
            const unsigned bslot  = (unsigned)(wlo % WROWS);
            const unsigned hibnd  = (unsigned)(HH - 1 - whi);   // 0 when whi==511

            #pragma unroll
            for (int s = 0; s < 4; s++) {
                const int h = h0 + s;
                if (h >= rhi) continue;
                const float c0 = cc0[s], c1 = cc1[s], m = cm[s];

                const float x = (float)tid + c0;
                const float y = (float)h   + c1;
                const float x0f = floorf(x), y0f = floorf(y);
                const float fx = x - x0f, fy = y - y0f;
                const int x0 = (int)x0f, y0 = (int)y0f;
                const int x1 = x0 + 1,   y1 = y0 + 1;

                // 1-D weight factors masked by image validity (unsigned range test)
                const float wx0 = ((unsigned)x0 < WW) ? (1.0f - fx) : 0.0f;
                const float wx1 = ((unsigned)x1 < WW) ? fx          : 0.0f;
                const float wy0 = ((unsigned)y0 < HH) ? (1.0f - fy) : 0.0f;
                const float wy1 = ((unsigned)y1 < HH) ? fy          : 0.0f;

                // fallback iff some tap row is in-image but outside the window
                const bool fb = ((unsigned)y0 < (unsigned)wlo) |
                                ((unsigned)y1 < (unsigned)wlo) |
                                ((unsigned)(y0 - whi - 1) < hibnd) |
                                ((unsigned)(y1 - whi - 1) < hibnd);

                float wv0, wv1;
                if (!fb) {
                    const int x0c = min(max(x0, 0), WW - 1);
                    const int x1c = min(max(x1, 0), WW - 1);
                    const int y0c = min(max(y0, wlo), whi);
                    const int y1c = min(max(y1, wlo), whi);
                    unsigned r0 = bslot + (unsigned)(y0c - wlo);
                    unsigned r1 = bslot + (unsigned)(y1c - wlo);
                    r0 = min(r0, r0 - WROWS);       // branch-free ring wrap
                    r1 = min(r1, r1 - WROWS);

                    const __half2 v00 = s_win[r0 * RSTRIDE + x0c];
                    const __half2 v10 = s_win[r0 * RSTRIDE + x1c];
                    const __half2 v01 = s_win[r1 * RSTRIDE + x0c];
                    const __half2 v11 = s_win[r1 * RSTRIDE + x1c];

                    const __half2 w00h = __float2half2_rn(wx0 * wy0);
                    const __half2 w10h = __float2half2_rn(wx1 * wy0);
                    const __half2 w01h = __float2half2_rn(wx0 * wy1);
                    const __half2 w11h = __float2half2_rn(wx1 * wy1);

                    __half2 a2 = __hmul2(w00h, v00);
                    a2 = __hfma2(w10h, v10, a2);
                    a2 = __hfma2(w01h, v01, a2);
                    a2 = __hfma2(w11h, v11, a2);
                    wv0 = __low2float(a2);
                    wv1 = __high2float(a2);
                } else {                           // rare (~0.4%) exact fp32 path
                    const int x0c = min(max(x0, 0), WW - 1);
                    const int x1c = min(max(x1, 0), WW - 1);
                    const int y0i = min(max(y0, 0), HH - 1);
                    const int y1i = min(max(y1, 0), HH - 1);
                    const int i00 = y0i * WW + x0c, i10 = y0i * WW + x1c;
                    const int i01 = y1i * WW + x0c, i11 = y1i * WW + x1c;
                    const float w00 = wx0 * wy0, w10 = wx1 * wy0;
                    const float w01 = wx0 * wy1, w11 = wx1 * wy1;
                    wv0 = w00 * __ldg(s0p + i00) + w10 * __ldg(s0p + i10) +
                          w01 * __ldg(s0p + i01) + w11 * __ldg(s0p + i11);
                    wv1 = w00 * __ldg(s1p + i00) + w10 * __ldg(s1p + i10) +
                          w01 * __ldg(s1p + i01) + w11 * __ldg(s1p + i11);
                }

                acc += m * (fabsf(wv0 + c0) + fabsf(wv1 + c1));
            }
        }
    }

    // Block reduction: warp shuffle, cross-warp, one double atomic per block.
    #pragma unroll
    for (int off = 16; off > 0; off >>= 1)
        acc += __shfl_xor_sync(0xFFFFFFFFu, acc, off);

    __shared__ float warp_sums[16];
    const int lane = tid & 31;
    const int wid  = tid >> 5;
    if (lane == 0) warp_sums[wid] = acc;
    __syncthreads();

    if (wid == 0) {
        float v = warp_sums[lane & 15];
        #pragma unroll
        for (int off = 8; off > 0; off >>= 1)
            v += __shfl_xor_sync(0xFFFFFFFFu, v, off);
        if (lane == 0) atomicAdd(&g_sum, (double)v);
    }
}

__global__ void finalize_kernel(const int* __restrict__ npf_ptr,
                                float* __restrict__ out) {
    float scale = 8.0f;
    if (npf_ptr) {
        int iv = *npf_ptr;
        if (iv >= 1 && iv <= (1 << 20)) {
            scale = (float)iv;                // stored as int32 (or low word of int64)
        } else {
            float fv = __int_as_float(iv);    // stored as float32
            scale = (fv > 0.0f && fv < 1.0e6f) ? fv : 8.0f;
        }
    }
    out[0] = (float)(g_sum / DENOM * (double)scale);
}

extern "C" void kernel_launch(void* const* d_in, const int* in_sizes, int n_in,
                              void* d_out, int out_size) {
    const float* flow     = (const float*)d_in[0];
    const float* flowback = (const float*)d_in[1];
    const float* mask_fw  = (const float*)d_in[2];
    const float* mask_bw  = (const float*)d_in[3];
    const int*   npf      = (n_in >= 5) ? (const int*)d_in[4] : nullptr;
    float* out = (float*)d_out;

    cudaFuncSetAttribute(loss_kernel,
                         cudaFuncAttributeMaxDynamicSharedMemorySize, SMEM_BYTES);

    init_kernel<<<1, 1>>>();
    loss_kernel<<<NBLK, 512, SMEM_BYTES>>>(flow, flowback, mask_fw, mask_bw);
    finalize_kernel<<<1, 1>>>(npf, out);
}